// round 6
// baseline (speedup 1.0000x reference)
#include <cuda_runtime.h>
#include <cuda_fp16.h>
#include <cstdint>

// ============================================================================
// Problem dims (fixed by the dataset)
// ============================================================================
#define BB 4
#define TT 256
#define UU 128
#define EE 512
#define DD 640
#define JJ 640
#define VV 1024

// ============================================================================
// Scratch (__device__ globals — allocation-free)
// ============================================================================
__device__ float g_enc_proj[BB * TT * JJ];   // (1024, 640) fp32
__device__ float g_dec_proj[BB * UU * JJ];   // (512, 640)  fp32
__device__ __half g_wt[VV * JJ];             // W_joint^T (1024, 640) fp16

// ============================================================================
// Fused prep kernel: both projections + W_joint transpose in ONE launch
// (they are independent; serial launches wasted ~40us of chip idle)
// blocks 0..159   : enc proj  (16 m-tiles x 10 n-tiles)
// blocks 160..239 : dec proj  (8 x 10)
// blocks 240..879 : transpose (32 v-tiles x 20 j-tiles)
// ============================================================================
__device__ __forceinline__ void proj_gemm_block(
    const float* __restrict__ A, const float* __restrict__ W,
    const float* __restrict__ bias, float* __restrict__ C,
    int K, int m0, int n0, float* As /*64x16*/, float* Ws /*16x64*/) {
    const int tid = threadIdx.x;
    const int tx = tid % 16, ty = tid / 16;
    const int N = JJ;

    float acc[4][4] = {};

    for (int k0 = 0; k0 < K; k0 += 16) {
        {
            int r = tid / 4, c = (tid % 4) * 4;
            float4 a4 = *(const float4*)&A[(size_t)(m0 + r) * K + k0 + c];
            *(float4*)&As[r * 16 + c] = a4;
            int rw = tid / 16, cw = (tid % 16) * 4;
            float4 w4 = *(const float4*)&W[(size_t)(k0 + rw) * N + n0 + cw];
            *(float4*)&Ws[rw * 64 + cw] = w4;
        }
        __syncthreads();
#pragma unroll
        for (int k = 0; k < 16; k++) {
            float a[4], w[4];
#pragma unroll
            for (int i = 0; i < 4; i++) a[i] = As[(ty * 4 + i) * 16 + k];
#pragma unroll
            for (int j = 0; j < 4; j++) w[j] = Ws[k * 64 + tx * 4 + j];
#pragma unroll
            for (int i = 0; i < 4; i++)
#pragma unroll
                for (int j = 0; j < 4; j++) acc[i][j] = fmaf(a[i], w[j], acc[i][j]);
        }
        __syncthreads();
    }
#pragma unroll
    for (int i = 0; i < 4; i++) {
#pragma unroll
        for (int j = 0; j < 4; j++) {
            int gm = m0 + ty * 4 + i, gn = n0 + tx * 4 + j;
            C[(size_t)gm * N + gn] = acc[i][j] + bias[gn];
        }
    }
}

__global__ void __launch_bounds__(256)
prep_kernel(const float* __restrict__ enc, const float* __restrict__ dec,
            const float* __restrict__ W_enc, const float* __restrict__ b_enc,
            const float* __restrict__ W_dec, const float* __restrict__ b_dec,
            const float* __restrict__ W_joint) {
    __shared__ float As[64 * 16];
    __shared__ float Ws[16 * 64];
    __shared__ float tile[32][33];
    const int bid = blockIdx.x;
    const int tid = threadIdx.x;

    if (bid < 160) {
        proj_gemm_block(enc, W_enc, b_enc, g_enc_proj, EE,
                        (bid / 10) * 64, (bid % 10) * 64, As, Ws);
    } else if (bid < 240) {
        int lb = bid - 160;
        proj_gemm_block(dec, W_dec, b_dec, g_dec_proj, DD,
                        (lb / 10) * 64, (lb % 10) * 64, As, Ws);
    } else {
        int lb = bid - 240;
        const int v0 = (lb & 31) * 32, j0 = (lb >> 5) * 32;
        const int tx = tid & 31, ty = tid >> 5;  // (32, 8)
#pragma unroll
        for (int i = 0; i < 4; i++) {
            int j = j0 + ty + i * 8;
            tile[ty + i * 8][tx] = W_joint[(size_t)j * VV + v0 + tx];
        }
        __syncthreads();
#pragma unroll
        for (int i = 0; i < 4; i++) {
            int v = v0 + ty + i * 8;
            int j = j0 + tx;
            g_wt[(size_t)v * JJ + j] = __float2half_rn(tile[tx][ty + i * 8]);
        }
    }
}

// ============================================================================
// Stage 2: fused tanh-joint + vocab GEMM via mma.sync (fp16 in, fp32 acc)
//
// Grid (8, 1024): CTA = 64 u-rows x 256 vocab cols, 256 threads = 8 warps
// (2 M x 4 N), warp tile 32x64. K = J = 640 in 64-chunks.
//
// A IS NEVER STAGED IN SMEM: each warp computes tanh(enc+dec) directly into
// its m16n8k16 A fragments (PTX-documented layout), removing the A STS/ldsm
// round trip and its barrier dependency. Only B is double-buffered via
// cp.async. Dec loads are software-pipelined one k16-step ahead.
// ============================================================================
#define KC 64
#define NCHUNK (JJ / KC)                 // 10
#define MT 64                            // M rows per CTA
#define STAGE_BYTES (256 * KC * 2)       // 32 KB (B only)
#define SM_TOTAL (2 * STAGE_BYTES)       // 64 KB (x2 CTAs = 128 KB/SM)

__device__ __forceinline__ uint32_t smem_u32(const void* p) {
    uint32_t r;
    asm("{ .reg .u64 t; cvta.to.shared.u64 t, %1; cvt.u32.u64 %0, t; }"
        : "=r"(r) : "l"(p));
    return r;
}

// rows are 128B wide; XOR bits[6:4] with row[2:0] for conflict-free ldmatrix
__device__ __forceinline__ uint32_t swz(uint32_t byte_off) {
    return byte_off ^ ((byte_off >> 3) & 0x70u);
}

__device__ __forceinline__ float tanh_approx(float x) {
    float y;
    asm("tanh.approx.f32 %0, %1;" : "=f"(y) : "f"(x));
    return y;
}

__device__ __forceinline__ uint32_t tanh2_pack(float2 e, float2 d) {
    float x0 = tanh_approx(e.x + d.x);
    float x1 = tanh_approx(e.y + d.y);
    __half2 h2 = __floats2half2_rn(x0, x1);
    return *(uint32_t*)&h2;
}

__device__ __forceinline__ void cp_async16(uint32_t dst, const void* src) {
    asm volatile("cp.async.cg.shared.global [%0], [%1], 16;"
                 :: "r"(dst), "l"(src));
}
#define CP_COMMIT() asm volatile("cp.async.commit_group;")
#define CP_WAIT0()  asm volatile("cp.async.wait_group 0;")

__device__ __forceinline__ void ldsm_x4(uint32_t addr, uint32_t& r0, uint32_t& r1,
                                        uint32_t& r2, uint32_t& r3) {
    asm volatile("ldmatrix.sync.aligned.m8n8.x4.shared.b16 {%0,%1,%2,%3}, [%4];"
                 : "=r"(r0), "=r"(r1), "=r"(r2), "=r"(r3) : "r"(addr));
}

__device__ __forceinline__ void mma16816(float* c, const uint32_t* a,
                                         const uint32_t* b) {
    asm volatile(
        "mma.sync.aligned.m16n8k16.row.col.f32.f16.f16.f32 "
        "{%0,%1,%2,%3}, {%4,%5,%6,%7}, {%8,%9}, {%0,%1,%2,%3};"
        : "+f"(c[0]), "+f"(c[1]), "+f"(c[2]), "+f"(c[3])
        : "r"(a[0]), "r"(a[1]), "r"(a[2]), "r"(a[3]), "r"(b[0]), "r"(b[1]));
}

// per-k16-step raw operands for the A fragments of one warp (2 m16 blocks)
struct AGenBuf {
    float2 e0, e1;        // enc at c0, c0+8
    float2 d[2][4];       // [mi][{r,c0},{r,c0+8},{r+8,c0},{r+8,c0+8}]
};

__global__ void __launch_bounds__(256, 2)
joint_vocab_kernel(const float* __restrict__ b_joint, float* __restrict__ out) {
    extern __shared__ __align__(128) char smem[];
    const uint32_t s0 = smem_u32(smem);   // stage s: B at s*STAGE_BYTES

    const int tid = threadIdx.x;
    const int lane = tid & 31;
    const int wid = tid >> 5;            // 0..7
    const int warp_m = wid & 1;          // m0 = warp_m*32
    const int warp_n = wid >> 1;         // 0..3 -> n0 = warp_n*64

    const int bx = blockIdx.x;           // 0..7
    const int v0 = (bx & 3) * 256;       // vocab tile
    const int u0 = (bx >> 2) * MT;       // u half
    const int bt = blockIdx.y;           // b*T + t
    const int b  = bt >> 8;              // T = 256

    const float* encrow = g_enc_proj + (size_t)bt * JJ;
    const float* decb   = g_dec_proj + ((size_t)b * UU + u0) * JJ;

    // A-fragment row pointers (documented m16n8k16 layout):
    // mi block rows: r = warp_m*32 + mi*16 + (lane>>2), and r+8
    const int fr = warp_m * 32 + (lane >> 2);
    const float* drow[2][2];
    drow[0][0] = decb + (size_t)(fr)      * JJ;   // mi=0, r
    drow[0][1] = decb + (size_t)(fr + 8)  * JJ;   // mi=0, r+8
    drow[1][0] = decb + (size_t)(fr + 16) * JJ;   // mi=1, r
    drow[1][1] = decb + (size_t)(fr + 24) * JJ;   // mi=1, r+8
    const int cl = (lane & 3) * 2;       // fragment column base within k16

    // B cp.async mapping: idx = tid + r*256 (r<8); n = idx>>3, g = idx&7 (16B)
    // B ldmatrix addressing
    const int b_nrow = warp_n * 64 + ((lane >> 4) << 3) + (lane & 7);
    const int b_kb   = ((lane >> 3) & 1) * 16;

    float acc[2][8][4];
#pragma unroll
    for (int mi = 0; mi < 2; mi++)
#pragma unroll
        for (int ni = 0; ni < 8; ni++)
#pragma unroll
            for (int c = 0; c < 4; c++) acc[mi][ni][c] = 0.0f;

    // ---- prologue: cp.async B(chunk 0) ----
    {
        const uint32_t sB = s0;
#pragma unroll
        for (int r = 0; r < 8; r++) {
            int idx = tid + r * 256;
            int n = idx >> 3, g = idx & 7;
            cp_async16(sB + swz((uint32_t)(n * 128 + g * 16)),
                       g_wt + (size_t)(v0 + n) * JJ + g * 8);
        }
        CP_COMMIT();
        CP_WAIT0();
        __syncthreads();
    }

    // ---- main pipeline ----
    for (int kc = 0; kc < NCHUNK; kc++) {
        const int j0 = kc * KC;
        const uint32_t cur = (uint32_t)(kc & 1) * STAGE_BYTES;
        const uint32_t nxt = (uint32_t)((kc + 1) & 1) * STAGE_BYTES;
        const bool has_next = (kc + 1) < NCHUNK;

        // -- cp.async B(k+1): in flight during this whole chunk --
        if (has_next) {
            const int j0n = j0 + KC;
            const uint32_t sBn = s0 + nxt;
#pragma unroll
            for (int r = 0; r < 8; r++) {
                int idx = tid + r * 256;
                int n = idx >> 3, g = idx & 7;
                cp_async16(sBn + swz((uint32_t)(n * 128 + g * 16)),
                           g_wt + (size_t)(v0 + n) * JJ + j0n + g * 8);
            }
            CP_COMMIT();
        }

        const uint32_t sBc = s0 + cur;

        // -- load raw A operands for ks=0 --
        AGenBuf buf;
        {
            const int c0 = j0 + cl;
            buf.e0 = *(const float2*)(encrow + c0);
            buf.e1 = *(const float2*)(encrow + c0 + 8);
#pragma unroll
            for (int mi = 0; mi < 2; mi++) {
                buf.d[mi][0] = *(const float2*)(drow[mi][0] + c0);
                buf.d[mi][1] = *(const float2*)(drow[mi][0] + c0 + 8);
                buf.d[mi][2] = *(const float2*)(drow[mi][1] + c0);
                buf.d[mi][3] = *(const float2*)(drow[mi][1] + c0 + 8);
            }
        }

#pragma unroll
        for (int ks = 0; ks < 4; ks++) {
            // -- tanh -> A fragments for this k16 step --
            uint32_t a[2][4];
#pragma unroll
            for (int mi = 0; mi < 2; mi++) {
                a[mi][0] = tanh2_pack(buf.e0, buf.d[mi][0]);  // r,   k0-7
                a[mi][1] = tanh2_pack(buf.e0, buf.d[mi][2]);  // r+8, k0-7
                a[mi][2] = tanh2_pack(buf.e1, buf.d[mi][1]);  // r,   k8-15
                a[mi][3] = tanh2_pack(buf.e1, buf.d[mi][3]);  // r+8, k8-15
            }

            // -- prefetch raw A operands for ks+1 (hidden under ldsm+MMA) --
            if (ks < 3) {
                const int c0 = j0 + (ks + 1) * 16 + cl;
                buf.e0 = *(const float2*)(encrow + c0);
                buf.e1 = *(const float2*)(encrow + c0 + 8);
#pragma unroll
                for (int mi = 0; mi < 2; mi++) {
                    buf.d[mi][0] = *(const float2*)(drow[mi][0] + c0);
                    buf.d[mi][1] = *(const float2*)(drow[mi][0] + c0 + 8);
                    buf.d[mi][2] = *(const float2*)(drow[mi][1] + c0);
                    buf.d[mi][3] = *(const float2*)(drow[mi][1] + c0 + 8);
                }
            }

            // -- B fragments + MMA --
            const int k0b = ks * 32;
            uint32_t bf[8][2];
#pragma unroll
            for (int nq = 0; nq < 4; nq++) {
                uint32_t addr = sBc +
                    swz((uint32_t)((b_nrow + nq * 16) * 128 + k0b + b_kb));
                ldsm_x4(addr, bf[nq * 2][0], bf[nq * 2][1],
                        bf[nq * 2 + 1][0], bf[nq * 2 + 1][1]);
            }
#pragma unroll
            for (int mi = 0; mi < 2; mi++)
#pragma unroll
                for (int ni = 0; ni < 8; ni++)
                    mma16816(acc[mi][ni], a[mi], bf[ni]);
        }

        if (has_next) CP_WAIT0();
        __syncthreads();
    }

    // ---- Epilogue: +bias, write fp32 ----
    {
        const int rowb = warp_m * 32 + (lane >> 2);
        const int colb = warp_n * 64 + (lane & 3) * 2;
        float* outbt = out + ((size_t)bt * UU + u0) * VV + v0;
        const float* bp = b_joint + v0;
#pragma unroll
        for (int ni = 0; ni < 8; ni++) {
            int c_ = colb + ni * 8;
            float2 b2 = *(const float2*)(bp + c_);
#pragma unroll
            for (int mi = 0; mi < 2; mi++) {
                int r_ = rowb + mi * 16;
                float2 o0 = { acc[mi][ni][0] + b2.x, acc[mi][ni][1] + b2.y };
                float2 o1 = { acc[mi][ni][2] + b2.x, acc[mi][ni][3] + b2.y };
                *(float2*)(outbt + (size_t)r_ * VV + c_) = o0;
                *(float2*)(outbt + (size_t)(r_ + 8) * VV + c_) = o1;
            }
        }
    }
}

// ============================================================================
// Launch
// ============================================================================
extern "C" void kernel_launch(void* const* d_in, const int* in_sizes, int n_in,
                              void* d_out, int out_size) {
    const float* enc     = (const float*)d_in[0];
    const float* dec     = (const float*)d_in[1];
    const float* W_enc   = (const float*)d_in[2];
    const float* b_enc   = (const float*)d_in[3];
    const float* W_dec   = (const float*)d_in[4];
    const float* b_dec   = (const float*)d_in[5];
    const float* W_joint = (const float*)d_in[6];
    const float* b_joint = (const float*)d_in[7];
    float* out = (float*)d_out;

    // fused projections + transpose
    prep_kernel<<<880, 256>>>(enc, dec, W_enc, b_enc, W_dec, b_dec, W_joint);

    // fused joint + vocab GEMM
    cudaFuncSetAttribute(joint_vocab_kernel,
                         cudaFuncAttributeMaxDynamicSharedMemorySize, SM_TOTAL);
    joint_vocab_kernel<<<dim3(8, BB * TT), 256, SM_TOTAL>>>(b_joint, out);
}

// round 7
// speedup vs baseline: 1.0003x; 1.0003x over previous
#include <cuda_runtime.h>
#include <cuda_fp16.h>
#include <cstdint>

// ============================================================================
// Problem dims (fixed by the dataset)
// ============================================================================
#define BB 4
#define TT 256
#define UU 128
#define EE 512
#define DD 640
#define JJ 640
#define VV 1024

// ============================================================================
// Scratch (__device__ globals — allocation-free)
// ============================================================================
__device__ float g_enc_proj[BB * TT * JJ];   // (1024, 640) fp32
__device__ float g_dec_proj[BB * UU * JJ];   // (512, 640)  fp32
__device__ __half g_wt[VV * JJ];             // W_joint^T (1024, 640) fp16

// ============================================================================
// Fused prep kernel: both projections + W_joint transpose in ONE launch
// (they are independent; serial launches wasted ~40us of chip idle)
// blocks 0..159   : enc proj  (16 m-tiles x 10 n-tiles)
// blocks 160..239 : dec proj  (8 x 10)
// blocks 240..879 : transpose (32 v-tiles x 20 j-tiles)
// ============================================================================
__device__ __forceinline__ void proj_gemm_block(
    const float* __restrict__ A, const float* __restrict__ W,
    const float* __restrict__ bias, float* __restrict__ C,
    int K, int m0, int n0, float* As /*64x16*/, float* Ws /*16x64*/) {
    const int tid = threadIdx.x;
    const int tx = tid % 16, ty = tid / 16;
    const int N = JJ;

    float acc[4][4] = {};

    for (int k0 = 0; k0 < K; k0 += 16) {
        {
            int r = tid / 4, c = (tid % 4) * 4;
            float4 a4 = *(const float4*)&A[(size_t)(m0 + r) * K + k0 + c];
            *(float4*)&As[r * 16 + c] = a4;
            int rw = tid / 16, cw = (tid % 16) * 4;
            float4 w4 = *(const float4*)&W[(size_t)(k0 + rw) * N + n0 + cw];
            *(float4*)&Ws[rw * 64 + cw] = w4;
        }
        __syncthreads();
#pragma unroll
        for (int k = 0; k < 16; k++) {
            float a[4], w[4];
#pragma unroll
            for (int i = 0; i < 4; i++) a[i] = As[(ty * 4 + i) * 16 + k];
#pragma unroll
            for (int j = 0; j < 4; j++) w[j] = Ws[k * 64 + tx * 4 + j];
#pragma unroll
            for (int i = 0; i < 4; i++)
#pragma unroll
                for (int j = 0; j < 4; j++) acc[i][j] = fmaf(a[i], w[j], acc[i][j]);
        }
        __syncthreads();
    }
#pragma unroll
    for (int i = 0; i < 4; i++) {
#pragma unroll
        for (int j = 0; j < 4; j++) {
            int gm = m0 + ty * 4 + i, gn = n0 + tx * 4 + j;
            C[(size_t)gm * N + gn] = acc[i][j] + bias[gn];
        }
    }
}

__global__ void __launch_bounds__(256)
prep_kernel(const float* __restrict__ enc, const float* __restrict__ dec,
            const float* __restrict__ W_enc, const float* __restrict__ b_enc,
            const float* __restrict__ W_dec, const float* __restrict__ b_dec,
            const float* __restrict__ W_joint) {
    __shared__ float As[64 * 16];
    __shared__ float Ws[16 * 64];
    __shared__ float tile[32][33];
    const int bid = blockIdx.x;
    const int tid = threadIdx.x;

    if (bid < 160) {
        proj_gemm_block(enc, W_enc, b_enc, g_enc_proj, EE,
                        (bid / 10) * 64, (bid % 10) * 64, As, Ws);
    } else if (bid < 240) {
        int lb = bid - 160;
        proj_gemm_block(dec, W_dec, b_dec, g_dec_proj, DD,
                        (lb / 10) * 64, (lb % 10) * 64, As, Ws);
    } else {
        int lb = bid - 240;
        const int v0 = (lb & 31) * 32, j0 = (lb >> 5) * 32;
        const int tx = tid & 31, ty = tid >> 5;  // (32, 8)
#pragma unroll
        for (int i = 0; i < 4; i++) {
            int j = j0 + ty + i * 8;
            tile[ty + i * 8][tx] = W_joint[(size_t)j * VV + v0 + tx];
        }
        __syncthreads();
#pragma unroll
        for (int i = 0; i < 4; i++) {
            int v = v0 + ty + i * 8;
            int j = j0 + tx;
            g_wt[(size_t)v * JJ + j] = __float2half_rn(tile[tx][ty + i * 8]);
        }
    }
}

// ============================================================================
// Stage 2: fused tanh-joint + vocab GEMM via mma.sync (fp16 in, fp32 acc)
//
// Grid (8, 1024): CTA = 64 u-rows x 256 vocab cols, 256 threads = 8 warps
// (2 M x 4 N), warp tile 32x64. K = J = 640 in 64-chunks.
//
// A IS NEVER STAGED IN SMEM: each warp computes tanh(enc+dec) directly into
// its m16n8k16 A fragments (PTX-documented layout), removing the A STS/ldsm
// round trip and its barrier dependency. Only B is double-buffered via
// cp.async. Dec loads are software-pipelined one k16-step ahead.
// ============================================================================
#define KC 64
#define NCHUNK (JJ / KC)                 // 10
#define MT 64                            // M rows per CTA
#define STAGE_BYTES (256 * KC * 2)       // 32 KB (B only)
#define SM_TOTAL (2 * STAGE_BYTES)       // 64 KB (x2 CTAs = 128 KB/SM)

__device__ __forceinline__ uint32_t smem_u32(const void* p) {
    uint32_t r;
    asm("{ .reg .u64 t; cvta.to.shared.u64 t, %1; cvt.u32.u64 %0, t; }"
        : "=r"(r) : "l"(p));
    return r;
}

// rows are 128B wide; XOR bits[6:4] with row[2:0] for conflict-free ldmatrix
__device__ __forceinline__ uint32_t swz(uint32_t byte_off) {
    return byte_off ^ ((byte_off >> 3) & 0x70u);
}

__device__ __forceinline__ float tanh_approx(float x) {
    float y;
    asm("tanh.approx.f32 %0, %1;" : "=f"(y) : "f"(x));
    return y;
}

__device__ __forceinline__ uint32_t tanh2_pack(float2 e, float2 d) {
    float x0 = tanh_approx(e.x + d.x);
    float x1 = tanh_approx(e.y + d.y);
    __half2 h2 = __floats2half2_rn(x0, x1);
    return *(uint32_t*)&h2;
}

__device__ __forceinline__ void cp_async16(uint32_t dst, const void* src) {
    asm volatile("cp.async.cg.shared.global [%0], [%1], 16;"
                 :: "r"(dst), "l"(src));
}
#define CP_COMMIT() asm volatile("cp.async.commit_group;")
#define CP_WAIT0()  asm volatile("cp.async.wait_group 0;")

__device__ __forceinline__ void ldsm_x4(uint32_t addr, uint32_t& r0, uint32_t& r1,
                                        uint32_t& r2, uint32_t& r3) {
    asm volatile("ldmatrix.sync.aligned.m8n8.x4.shared.b16 {%0,%1,%2,%3}, [%4];"
                 : "=r"(r0), "=r"(r1), "=r"(r2), "=r"(r3) : "r"(addr));
}

__device__ __forceinline__ void mma16816(float* c, const uint32_t* a,
                                         const uint32_t* b) {
    asm volatile(
        "mma.sync.aligned.m16n8k16.row.col.f32.f16.f16.f32 "
        "{%0,%1,%2,%3}, {%4,%5,%6,%7}, {%8,%9}, {%0,%1,%2,%3};"
        : "+f"(c[0]), "+f"(c[1]), "+f"(c[2]), "+f"(c[3])
        : "r"(a[0]), "r"(a[1]), "r"(a[2]), "r"(a[3]), "r"(b[0]), "r"(b[1]));
}

// per-k16-step raw operands for the A fragments of one warp (2 m16 blocks)
struct AGenBuf {
    float2 e0, e1;        // enc at c0, c0+8
    float2 d[2][4];       // [mi][{r,c0},{r,c0+8},{r+8,c0},{r+8,c0+8}]
};

__global__ void __launch_bounds__(256, 2)
joint_vocab_kernel(const float* __restrict__ b_joint, float* __restrict__ out) {
    extern __shared__ __align__(128) char smem[];
    const uint32_t s0 = smem_u32(smem);   // stage s: B at s*STAGE_BYTES

    const int tid = threadIdx.x;
    const int lane = tid & 31;
    const int wid = tid >> 5;            // 0..7
    const int warp_m = wid & 1;          // m0 = warp_m*32
    const int warp_n = wid >> 1;         // 0..3 -> n0 = warp_n*64

    const int bx = blockIdx.x;           // 0..7
    const int v0 = (bx & 3) * 256;       // vocab tile
    const int u0 = (bx >> 2) * MT;       // u half
    const int bt = blockIdx.y;           // b*T + t
    const int b  = bt >> 8;              // T = 256

    const float* encrow = g_enc_proj + (size_t)bt * JJ;
    const float* decb   = g_dec_proj + ((size_t)b * UU + u0) * JJ;

    // A-fragment row pointers (documented m16n8k16 layout):
    // mi block rows: r = warp_m*32 + mi*16 + (lane>>2), and r+8
    const int fr = warp_m * 32 + (lane >> 2);
    const float* drow[2][2];
    drow[0][0] = decb + (size_t)(fr)      * JJ;   // mi=0, r
    drow[0][1] = decb + (size_t)(fr + 8)  * JJ;   // mi=0, r+8
    drow[1][0] = decb + (size_t)(fr + 16) * JJ;   // mi=1, r
    drow[1][1] = decb + (size_t)(fr + 24) * JJ;   // mi=1, r+8
    const int cl = (lane & 3) * 2;       // fragment column base within k16

    // B cp.async mapping: idx = tid + r*256 (r<8); n = idx>>3, g = idx&7 (16B)
    // B ldmatrix addressing
    const int b_nrow = warp_n * 64 + ((lane >> 4) << 3) + (lane & 7);
    const int b_kb   = ((lane >> 3) & 1) * 16;

    float acc[2][8][4];
#pragma unroll
    for (int mi = 0; mi < 2; mi++)
#pragma unroll
        for (int ni = 0; ni < 8; ni++)
#pragma unroll
            for (int c = 0; c < 4; c++) acc[mi][ni][c] = 0.0f;

    // ---- prologue: cp.async B(chunk 0) ----
    {
        const uint32_t sB = s0;
#pragma unroll
        for (int r = 0; r < 8; r++) {
            int idx = tid + r * 256;
            int n = idx >> 3, g = idx & 7;
            cp_async16(sB + swz((uint32_t)(n * 128 + g * 16)),
                       g_wt + (size_t)(v0 + n) * JJ + g * 8);
        }
        CP_COMMIT();
        CP_WAIT0();
        __syncthreads();
    }

    // ---- main pipeline ----
    for (int kc = 0; kc < NCHUNK; kc++) {
        const int j0 = kc * KC;
        const uint32_t cur = (uint32_t)(kc & 1) * STAGE_BYTES;
        const uint32_t nxt = (uint32_t)((kc + 1) & 1) * STAGE_BYTES;
        const bool has_next = (kc + 1) < NCHUNK;

        // -- cp.async B(k+1): in flight during this whole chunk --
        if (has_next) {
            const int j0n = j0 + KC;
            const uint32_t sBn = s0 + nxt;
#pragma unroll
            for (int r = 0; r < 8; r++) {
                int idx = tid + r * 256;
                int n = idx >> 3, g = idx & 7;
                cp_async16(sBn + swz((uint32_t)(n * 128 + g * 16)),
                           g_wt + (size_t)(v0 + n) * JJ + j0n + g * 8);
            }
            CP_COMMIT();
        }

        const uint32_t sBc = s0 + cur;

        // -- load raw A operands for ks=0 --
        AGenBuf buf;
        {
            const int c0 = j0 + cl;
            buf.e0 = *(const float2*)(encrow + c0);
            buf.e1 = *(const float2*)(encrow + c0 + 8);
#pragma unroll
            for (int mi = 0; mi < 2; mi++) {
                buf.d[mi][0] = *(const float2*)(drow[mi][0] + c0);
                buf.d[mi][1] = *(const float2*)(drow[mi][0] + c0 + 8);
                buf.d[mi][2] = *(const float2*)(drow[mi][1] + c0);
                buf.d[mi][3] = *(const float2*)(drow[mi][1] + c0 + 8);
            }
        }

#pragma unroll
        for (int ks = 0; ks < 4; ks++) {
            // -- tanh -> A fragments for this k16 step --
            uint32_t a[2][4];
#pragma unroll
            for (int mi = 0; mi < 2; mi++) {
                a[mi][0] = tanh2_pack(buf.e0, buf.d[mi][0]);  // r,   k0-7
                a[mi][1] = tanh2_pack(buf.e0, buf.d[mi][2]);  // r+8, k0-7
                a[mi][2] = tanh2_pack(buf.e1, buf.d[mi][1]);  // r,   k8-15
                a[mi][3] = tanh2_pack(buf.e1, buf.d[mi][3]);  // r+8, k8-15
            }

            // -- prefetch raw A operands for ks+1 (hidden under ldsm+MMA) --
            if (ks < 3) {
                const int c0 = j0 + (ks + 1) * 16 + cl;
                buf.e0 = *(const float2*)(encrow + c0);
                buf.e1 = *(const float2*)(encrow + c0 + 8);
#pragma unroll
                for (int mi = 0; mi < 2; mi++) {
                    buf.d[mi][0] = *(const float2*)(drow[mi][0] + c0);
                    buf.d[mi][1] = *(const float2*)(drow[mi][0] + c0 + 8);
                    buf.d[mi][2] = *(const float2*)(drow[mi][1] + c0);
                    buf.d[mi][3] = *(const float2*)(drow[mi][1] + c0 + 8);
                }
            }

            // -- B fragments + MMA --
            const int k0b = ks * 32;
            uint32_t bf[8][2];
#pragma unroll
            for (int nq = 0; nq < 4; nq++) {
                uint32_t addr = sBc +
                    swz((uint32_t)((b_nrow + nq * 16) * 128 + k0b + b_kb));
                ldsm_x4(addr, bf[nq * 2][0], bf[nq * 2][1],
                        bf[nq * 2 + 1][0], bf[nq * 2 + 1][1]);
            }
#pragma unroll
            for (int mi = 0; mi < 2; mi++)
#pragma unroll
                for (int ni = 0; ni < 8; ni++)
                    mma16816(acc[mi][ni], a[mi], bf[ni]);
        }

        if (has_next) CP_WAIT0();
        __syncthreads();
    }

    // ---- Epilogue: +bias, write fp32 ----
    {
        const int rowb = warp_m * 32 + (lane >> 2);
        const int colb = warp_n * 64 + (lane & 3) * 2;
        float* outbt = out + ((size_t)bt * UU + u0) * VV + v0;
        const float* bp = b_joint + v0;
#pragma unroll
        for (int ni = 0; ni < 8; ni++) {
            int c_ = colb + ni * 8;
            float2 b2 = *(const float2*)(bp + c_);
#pragma unroll
            for (int mi = 0; mi < 2; mi++) {
                int r_ = rowb + mi * 16;
                float2 o0 = { acc[mi][ni][0] + b2.x, acc[mi][ni][1] + b2.y };
                float2 o1 = { acc[mi][ni][2] + b2.x, acc[mi][ni][3] + b2.y };
                *(float2*)(outbt + (size_t)r_ * VV + c_) = o0;
                *(float2*)(outbt + (size_t)(r_ + 8) * VV + c_) = o1;
            }
        }
    }
}

// ============================================================================
// Launch
// ============================================================================
extern "C" void kernel_launch(void* const* d_in, const int* in_sizes, int n_in,
                              void* d_out, int out_size) {
    const float* enc     = (const float*)d_in[0];
    const float* dec     = (const float*)d_in[1];
    const float* W_enc   = (const float*)d_in[2];
    const float* b_enc   = (const float*)d_in[3];
    const float* W_dec   = (const float*)d_in[4];
    const float* b_dec   = (const float*)d_in[5];
    const float* W_joint = (const float*)d_in[6];
    const float* b_joint = (const float*)d_in[7];
    float* out = (float*)d_out;

    // fused projections + transpose
    prep_kernel<<<880, 256>>>(enc, dec, W_enc, b_enc, W_dec, b_dec, W_joint);

    // fused joint + vocab GEMM
    cudaFuncSetAttribute(joint_vocab_kernel,
                         cudaFuncAttributeMaxDynamicSharedMemorySize, SM_TOTAL);
    joint_vocab_kernel<<<dim3(8, BB * TT), 256, SM_TOTAL>>>(b_joint, out);
}

// round 8
// speedup vs baseline: 1.7829x; 1.7824x over previous
#include <cuda_runtime.h>
#include <cuda_fp16.h>
#include <cstdint>

// ============================================================================
// Problem dims (fixed by the dataset)
// ============================================================================
#define BB 4
#define TT 256
#define UU 128
#define EE 512
#define DD 640
#define JJ 640
#define VV 1024

// ============================================================================
// Scratch (__device__ globals — allocation-free)
// ============================================================================
__device__ float g_enc_proj[BB * TT * JJ];       // (1024, 640) fp32
__device__ float g_dec_proj[BB * UU * JJ];       // (512, 640)  fp32
__device__ __half g_wt[VV * JJ];                 // W_joint^T (1024, 640) fp16
__device__ __half g_joint[(size_t)BB * TT * UU * JJ];  // tanh joint, fp16 (168MB)

// ============================================================================
// Fused prep kernel: both projections + W_joint transpose in ONE launch
// blocks 0..159   : enc proj  (16 m-tiles x 10 n-tiles)
// blocks 160..239 : dec proj  (8 x 10)
// blocks 240..879 : transpose (32 v-tiles x 20 j-tiles)
// ============================================================================
__device__ __forceinline__ void proj_gemm_block(
    const float* __restrict__ A, const float* __restrict__ W,
    const float* __restrict__ bias, float* __restrict__ C,
    int K, int m0, int n0, float* As /*64x16*/, float* Ws /*16x64*/) {
    const int tid = threadIdx.x;
    const int tx = tid % 16, ty = tid / 16;
    const int N = JJ;

    float acc[4][4] = {};

    for (int k0 = 0; k0 < K; k0 += 16) {
        {
            int r = tid / 4, c = (tid % 4) * 4;
            float4 a4 = *(const float4*)&A[(size_t)(m0 + r) * K + k0 + c];
            *(float4*)&As[r * 16 + c] = a4;
            int rw = tid / 16, cw = (tid % 16) * 4;
            float4 w4 = *(const float4*)&W[(size_t)(k0 + rw) * N + n0 + cw];
            *(float4*)&Ws[rw * 64 + cw] = w4;
        }
        __syncthreads();
#pragma unroll
        for (int k = 0; k < 16; k++) {
            float a[4], w[4];
#pragma unroll
            for (int i = 0; i < 4; i++) a[i] = As[(ty * 4 + i) * 16 + k];
#pragma unroll
            for (int j = 0; j < 4; j++) w[j] = Ws[k * 64 + tx * 4 + j];
#pragma unroll
            for (int i = 0; i < 4; i++)
#pragma unroll
                for (int j = 0; j < 4; j++) acc[i][j] = fmaf(a[i], w[j], acc[i][j]);
        }
        __syncthreads();
    }
#pragma unroll
    for (int i = 0; i < 4; i++) {
#pragma unroll
        for (int j = 0; j < 4; j++) {
            int gm = m0 + ty * 4 + i, gn = n0 + tx * 4 + j;
            C[(size_t)gm * N + gn] = acc[i][j] + bias[gn];
        }
    }
}

__global__ void __launch_bounds__(256)
prep_kernel(const float* __restrict__ enc, const float* __restrict__ dec,
            const float* __restrict__ W_enc, const float* __restrict__ b_enc,
            const float* __restrict__ W_dec, const float* __restrict__ b_dec,
            const float* __restrict__ W_joint) {
    __shared__ float As[64 * 16];
    __shared__ float Ws[16 * 64];
    __shared__ float tile[32][33];
    const int bid = blockIdx.x;
    const int tid = threadIdx.x;

    if (bid < 160) {
        proj_gemm_block(enc, W_enc, b_enc, g_enc_proj, EE,
                        (bid / 10) * 64, (bid % 10) * 64, As, Ws);
    } else if (bid < 240) {
        int lb = bid - 160;
        proj_gemm_block(dec, W_dec, b_dec, g_dec_proj, DD,
                        (lb / 10) * 64, (lb % 10) * 64, As, Ws);
    } else {
        int lb = bid - 240;
        const int v0 = (lb & 31) * 32, j0 = (lb >> 5) * 32;
        const int tx = tid & 31, ty = tid >> 5;  // (32, 8)
#pragma unroll
        for (int i = 0; i < 4; i++) {
            int j = j0 + ty + i * 8;
            tile[ty + i * 8][tx] = W_joint[(size_t)j * VV + v0 + tx];
        }
        __syncthreads();
#pragma unroll
        for (int i = 0; i < 4; i++) {
            int v = v0 + ty + i * 8;
            int j = j0 + tx;
            g_wt[(size_t)v * JJ + j] = __float2half_rn(tile[tx][ty + i * 8]);
        }
    }
}

// ============================================================================
// Stage 1c: generate the full tanh joint tensor in fp16 (HBM-write bound)
// grid = (B*T), block = (160, 4). Thread (jq, us) covers j = 4*jq,
// u = us + 4*ui. Writes 8B (4 fp16) coalesced along j.
// ============================================================================
__device__ __forceinline__ float tanh_approx(float x) {
    float y;
    asm("tanh.approx.f32 %0, %1;" : "=f"(y) : "f"(x));
    return y;
}

__global__ void __launch_bounds__(640)
gen_joint_kernel() {
    const int bt = blockIdx.x;
    const int b  = bt >> 8;              // T = 256
    const int j  = threadIdx.x * 4;      // 0..636
    const int us = threadIdx.y;          // 0..3

    float4 e4 = *(const float4*)(g_enc_proj + (size_t)bt * JJ + j);
    __half* outrow = g_joint + ((size_t)bt * UU) * JJ + j;

#pragma unroll 4
    for (int ui = 0; ui < 32; ui++) {
        int u = us + ui * 4;
        float4 d4 = *(const float4*)(g_dec_proj + ((size_t)b * UU + u) * JJ + j);
        __half2 h0 = __floats2half2_rn(tanh_approx(e4.x + d4.x),
                                       tanh_approx(e4.y + d4.y));
        __half2 h1 = __floats2half2_rn(tanh_approx(e4.z + d4.z),
                                       tanh_approx(e4.w + d4.w));
        uint2 pk = { *(uint32_t*)&h0, *(uint32_t*)&h1 };
        *(uint2*)(outrow + (size_t)u * JJ) = pk;
    }
}

// ============================================================================
// Stage 2: pure GEMM via mma.sync (fp16 in, fp32 acc)
//   out[bt,u,v] = sum_j joint[bt,u,j] * wt[v,j] + bias[v]
//
// Grid (8, 1024): CTA = 64 u-rows x 256 vocab cols, 256 threads = 8 warps
// (2 M x 4 N), warp tile 32x64. K = J = 640 in 64-chunks.
// A and B both double-buffered via cp.async; no compute between MMA phases.
// 2 CTAs co-resident per SM.
// ============================================================================
#define KC 64
#define NCHUNK (JJ / KC)                 // 10
#define MT 64                            // M rows per CTA
#define SM_A_BYTES (MT * KC * 2)         // 8 KB
#define SM_B_BYTES (256 * KC * 2)        // 32 KB
#define STAGE_BYTES (SM_A_BYTES + SM_B_BYTES)   // 40 KB
#define SM_TOTAL (2 * STAGE_BYTES)       // 80 KB (x2 CTAs = 160 KB/SM)

__device__ __forceinline__ uint32_t smem_u32(const void* p) {
    uint32_t r;
    asm("{ .reg .u64 t; cvta.to.shared.u64 t, %1; cvt.u32.u64 %0, t; }"
        : "=r"(r) : "l"(p));
    return r;
}

// rows are 128B wide; XOR bits[6:4] with row[2:0] for conflict-free ldmatrix
__device__ __forceinline__ uint32_t swz(uint32_t byte_off) {
    return byte_off ^ ((byte_off >> 3) & 0x70u);
}

__device__ __forceinline__ void cp_async16(uint32_t dst, const void* src) {
    asm volatile("cp.async.cg.shared.global [%0], [%1], 16;"
                 :: "r"(dst), "l"(src));
}
#define CP_COMMIT() asm volatile("cp.async.commit_group;")
#define CP_WAIT0()  asm volatile("cp.async.wait_group 0;")

__device__ __forceinline__ void ldsm_x4(uint32_t addr, uint32_t& r0, uint32_t& r1,
                                        uint32_t& r2, uint32_t& r3) {
    asm volatile("ldmatrix.sync.aligned.m8n8.x4.shared.b16 {%0,%1,%2,%3}, [%4];"
                 : "=r"(r0), "=r"(r1), "=r"(r2), "=r"(r3) : "r"(addr));
}

__device__ __forceinline__ void mma16816(float* c, const uint32_t* a,
                                         const uint32_t* b) {
    asm volatile(
        "mma.sync.aligned.m16n8k16.row.col.f32.f16.f16.f32 "
        "{%0,%1,%2,%3}, {%4,%5,%6,%7}, {%8,%9}, {%0,%1,%2,%3};"
        : "+f"(c[0]), "+f"(c[1]), "+f"(c[2]), "+f"(c[3])
        : "r"(a[0]), "r"(a[1]), "r"(a[2]), "r"(a[3]), "r"(b[0]), "r"(b[1]));
}

__global__ void __launch_bounds__(256, 2)
joint_vocab_kernel(const float* __restrict__ b_joint, float* __restrict__ out) {
    extern __shared__ __align__(128) char smem[];
    const uint32_t s0 = smem_u32(smem);
    // stage s: A at s*STAGE_BYTES, B at s*STAGE_BYTES + SM_A_BYTES

    const int tid = threadIdx.x;
    const int lane = tid & 31;
    const int wid = tid >> 5;            // 0..7
    const int warp_m = wid & 1;          // m0 = warp_m*32
    const int warp_n = wid >> 1;         // 0..3 -> n0 = warp_n*64

    const int bx = blockIdx.x;           // 0..7
    const int v0 = (bx & 3) * 256;       // vocab tile
    const int u0 = (bx >> 2) * MT;       // u half
    const int bt = blockIdx.y;           // b*T + t

    const __half* arow = g_joint + ((size_t)bt * UU + u0) * JJ;

    // A cp.async mapping: idx = tid + r*256 (r<2); u = idx>>3, g = idx&7 (16B)
    // B cp.async mapping: idx = tid + r*256 (r<8); n = idx>>3, g = idx&7 (16B)

    // ldmatrix fragment addressing (within a stage)
    const int a_row = warp_m * 32 + (lane & 15);
    const int a_kb  = (lane >> 4) * 16;
    const int b_nrow = warp_n * 64 + ((lane >> 4) << 3) + (lane & 7);
    const int b_kb   = ((lane >> 3) & 1) * 16;

    float acc[2][8][4];
#pragma unroll
    for (int mi = 0; mi < 2; mi++)
#pragma unroll
        for (int ni = 0; ni < 8; ni++)
#pragma unroll
            for (int c = 0; c < 4; c++) acc[mi][ni][c] = 0.0f;

    // ---- prologue: cp.async A+B (chunk 0) ----
    {
        const uint32_t sA = s0;
        const uint32_t sB = s0 + SM_A_BYTES;
#pragma unroll
        for (int r = 0; r < 2; r++) {
            int idx = tid + r * 256;
            int u = idx >> 3, g = idx & 7;
            cp_async16(sA + swz((uint32_t)(u * 128 + g * 16)),
                       arow + (size_t)u * JJ + g * 8);
        }
#pragma unroll
        for (int r = 0; r < 8; r++) {
            int idx = tid + r * 256;
            int n = idx >> 3, g = idx & 7;
            cp_async16(sB + swz((uint32_t)(n * 128 + g * 16)),
                       g_wt + (size_t)(v0 + n) * JJ + g * 8);
        }
        CP_COMMIT();
        CP_WAIT0();
        __syncthreads();
    }

    // ---- main pipeline ----
    for (int kc = 0; kc < NCHUNK; kc++) {
        const uint32_t cur = (uint32_t)(kc & 1) * STAGE_BYTES;
        const uint32_t nxt = (uint32_t)((kc + 1) & 1) * STAGE_BYTES;
        const bool has_next = (kc + 1) < NCHUNK;

        // -- cp.async A+B (k+1): in flight during this whole chunk --
        if (has_next) {
            const int j0n = (kc + 1) * KC;
            const uint32_t sAn = s0 + nxt;
            const uint32_t sBn = s0 + nxt + SM_A_BYTES;
#pragma unroll
            for (int r = 0; r < 2; r++) {
                int idx = tid + r * 256;
                int u = idx >> 3, g = idx & 7;
                cp_async16(sAn + swz((uint32_t)(u * 128 + g * 16)),
                           arow + (size_t)u * JJ + j0n + g * 8);
            }
#pragma unroll
            for (int r = 0; r < 8; r++) {
                int idx = tid + r * 256;
                int n = idx >> 3, g = idx & 7;
                cp_async16(sBn + swz((uint32_t)(n * 128 + g * 16)),
                           g_wt + (size_t)(v0 + n) * JJ + j0n + g * 8);
            }
            CP_COMMIT();
        }

        // -- MMA on current stage --
        const uint32_t sAc = s0 + cur;
        const uint32_t sBc = s0 + cur + SM_A_BYTES;
#pragma unroll
        for (int ks = 0; ks < 4; ks++) {
            const int k0b = ks * 32;
            uint32_t a[2][4];
#pragma unroll
            for (int mi = 0; mi < 2; mi++) {
                uint32_t addr = sAc +
                    swz((uint32_t)((a_row + mi * 16) * 128 + k0b + a_kb));
                ldsm_x4(addr, a[mi][0], a[mi][1], a[mi][2], a[mi][3]);
            }
            uint32_t bf[8][2];
#pragma unroll
            for (int nq = 0; nq < 4; nq++) {
                uint32_t addr = sBc +
                    swz((uint32_t)((b_nrow + nq * 16) * 128 + k0b + b_kb));
                ldsm_x4(addr, bf[nq * 2][0], bf[nq * 2][1],
                        bf[nq * 2 + 1][0], bf[nq * 2 + 1][1]);
            }
#pragma unroll
            for (int mi = 0; mi < 2; mi++)
#pragma unroll
                for (int ni = 0; ni < 8; ni++)
                    mma16816(acc[mi][ni], a[mi], bf[ni]);
        }

        if (has_next) CP_WAIT0();
        __syncthreads();
    }

    // ---- Epilogue: +bias, write fp32 ----
    {
        const int rowb = warp_m * 32 + (lane >> 2);
        const int colb = warp_n * 64 + (lane & 3) * 2;
        float* outbt = out + ((size_t)bt * UU + u0) * VV + v0;
        const float* bp = b_joint + v0;
#pragma unroll
        for (int ni = 0; ni < 8; ni++) {
            int c_ = colb + ni * 8;
            float2 b2 = *(const float2*)(bp + c_);
#pragma unroll
            for (int mi = 0; mi < 2; mi++) {
                int r_ = rowb + mi * 16;
                float2 o0 = { acc[mi][ni][0] + b2.x, acc[mi][ni][1] + b2.y };
                float2 o1 = { acc[mi][ni][2] + b2.x, acc[mi][ni][3] + b2.y };
                *(float2*)(outbt + (size_t)r_ * VV + c_) = o0;
                *(float2*)(outbt + (size_t)(r_ + 8) * VV + c_) = o1;
            }
        }
    }
}

// ============================================================================
// Launch
// ============================================================================
extern "C" void kernel_launch(void* const* d_in, const int* in_sizes, int n_in,
                              void* d_out, int out_size) {
    const float* enc     = (const float*)d_in[0];
    const float* dec     = (const float*)d_in[1];
    const float* W_enc   = (const float*)d_in[2];
    const float* b_enc   = (const float*)d_in[3];
    const float* W_dec   = (const float*)d_in[4];
    const float* b_dec   = (const float*)d_in[5];
    const float* W_joint = (const float*)d_in[6];
    const float* b_joint = (const float*)d_in[7];
    float* out = (float*)d_out;

    // fused projections + transpose
    prep_kernel<<<880, 256>>>(enc, dec, W_enc, b_enc, W_dec, b_dec, W_joint);

    // full tanh joint tensor (fp16, HBM)
    gen_joint_kernel<<<BB * TT, dim3(160, 4)>>>();

    // pure vocab GEMM
    cudaFuncSetAttribute(joint_vocab_kernel,
                         cudaFuncAttributeMaxDynamicSharedMemorySize, SM_TOTAL);
    joint_vocab_kernel<<<dim3(8, BB * TT), 256, SM_TOTAL>>>(b_joint, out);
}